// round 8
// baseline (speedup 1.0000x reference)
#include <cuda_runtime.h>
#include <cstdint>

// SparseConv1D: out[b,o,l] = sum_i sum_k w[o,i,k] * x[b,i,l+d_k] (zero pad OOR)
// x: [16,64,4096] f32, w: [64,64,32] f32, out: [16,64,4096] f32.
//
// Two kernels in one graph:
//  1) prepass: build padded, batch-interleaved copy of x in __device__ scratch:
//     g_xi[bp][i][j] = (x[2bp,i,j-512], x[2bp+1,i,j-512]), zeros outside.
//  2) main: per input channel, cp.async (LDGSTS) the 1280-float2 window slice
//     into a double-buffered smem window while computing the current channel.
//     FFMA2 lanes pair batches -> every tap offset is one aligned LDS.64.

#define K_TAPS   32
#define CIN      64
#define COUT     64
#define LEN      4096
#define BATCH    16
#define LOWPAD   512
#define PADLEN   (LEN + 768)            // 4864 padded slots
#define THREADS  128
#define NOUT     8
#define NPAIR    4
#define LTILE    (THREADS * NPAIR)      // 512 positions per block
#define WIN2     (LTILE + 768)          // 1280 float2 window slots
#define CHUNKS   (WIN2 * 8 / 16)        // 640 16B cp.async chunks
#define NBP      (BATCH / 2)            // 8 batch pairs

__device__ __align__(16) float2 g_xi[NBP * CIN * PADLEN];   // ~19.9 MB

// Packed fp32x2 FMA (Blackwell FFMA2), PTX-only.
__device__ __forceinline__ float2 ffma2(float2 a, float2 b, float2 c) {
    float2 d;
    asm("fma.rn.f32x2 %0, %1, %2, %3;"
        : "=l"(*reinterpret_cast<unsigned long long*>(&d))
        : "l"(*reinterpret_cast<unsigned long long*>(&a)),
          "l"(*reinterpret_cast<unsigned long long*>(&b)),
          "l"(*reinterpret_cast<unsigned long long*>(&c)));
    return d;
}

__device__ __forceinline__ void cp_async16(unsigned int dst_smem, const void* src) {
    asm volatile("cp.async.cg.shared.global [%0], [%1], 16;"
                 :: "r"(dst_smem), "l"(src));
}
__device__ __forceinline__ void cp_async_commit() {
    asm volatile("cp.async.commit_group;");
}
__device__ __forceinline__ void cp_async_wait_all() {
    asm volatile("cp.async.wait_group 0;");
}
__device__ __forceinline__ unsigned int smem_u32(const void* p) {
    unsigned int a;
    asm("{ .reg .u64 t; cvta.to.shared.u64 t, %1; cvt.u32.u64 %0, t; }"
        : "=r"(a) : "l"(p));
    return a;
}

// ---- prepass: pad + batch-interleave x --------------------------------
__global__ void interleave_kernel(const float* __restrict__ x) {
    int idx = blockIdx.x * blockDim.x + threadIdx.x;     // over NBP*CIN*PADLEN
    if (idx >= NBP * CIN * PADLEN) return;
    int j  = idx % PADLEN;
    int ci = idx / PADLEN;          // bp*CIN + i
    int bp = ci / CIN;
    int g  = j - LOWPAD;
    float a = 0.f, b = 0.f;
    if ((unsigned)g < (unsigned)LEN) {
        const float* base = x + ((size_t)(2 * bp) * CIN + (ci % CIN)) * LEN + g;
        a = base[0];
        b = base[CIN * LEN];
    }
    g_xi[idx] = make_float2(a, b);
}

// ---- main kernel -------------------------------------------------------
__global__ __launch_bounds__(THREADS, 4)
void sk_conv_kernel(const float* __restrict__ w,
                    float* __restrict__ out) {
    constexpr int SK[K_TAPS] = {
        -512,-256,-128,-96,-64,-48,-32,-24,-16,-12,-8,-6,-4,-3,-2,-1,
         0,1,2,3,4,6,8,12,16,24,32,48,64,96,128,256
    };

    __shared__ __align__(16) float2 win[2][WIN2];          // 20 KB
    __shared__ float4 wq[2][(K_TAPS / 4) * NOUT];          // 2 KB

    const int tid = threadIdx.x;
    const int l0  = blockIdx.x * LTILE;
    const int o0  = blockIdx.y * NOUT;
    const int bp  = blockIdx.z;

    const float2* xrow = g_xi + ((size_t)bp * CIN) * PADLEN + l0;
    const unsigned int win_s0 = smem_u32(&win[0][0]);
    const unsigned int win_s1 = smem_u32(&win[1][0]);

    // weight staging lane (threads 0..63): wq[.][kk4*8+o] = w[o0+o,i,4kk4..+3]
    const int so   = tid & 7;
    const int skk4 = tid >> 3;
    const float* wsrc = w + ((size_t)(o0 + so) * CIN) * K_TAPS + 4 * skk4;

    // ---- prologue: window 0 + weights for i=0; prefetch weights i=1 ----
#pragma unroll
    for (int it = 0; it < CHUNKS / THREADS; ++it) {
        int c = tid + it * THREADS;
        cp_async16(win_s0 + c * 16, (const char*)xrow + c * 16);
    }
    cp_async_commit();

    float4 wpre1;
    if (tid < 64) {
        float4 wpre0 = *reinterpret_cast<const float4*>(wsrc);     // i=0
        wpre1 = *reinterpret_cast<const float4*>(wsrc + K_TAPS);   // i=1
        wq[0][skk4 * NOUT + so] = wpre0;
    }
    cp_async_wait_all();
    __syncthreads();

    float2 acc[NOUT][NPAIR];
#pragma unroll
    for (int o = 0; o < NOUT; ++o)
#pragma unroll
        for (int p = 0; p < NPAIR; ++p) acc[o][p] = make_float2(0.f, 0.f);

    for (int i = 0; i < CIN; ++i) {
        const int cur = i & 1, nxt = cur ^ 1;
        const bool more = (i + 1 < CIN);

        // ---- launch async fill of next channel's window + stage weights
        if (more) {
            const char* src = (const char*)(xrow + (size_t)(i + 1) * PADLEN);
            const unsigned int dst = nxt ? win_s1 : win_s0;
#pragma unroll
            for (int it = 0; it < CHUNKS / THREADS; ++it) {
                int c = tid + it * THREADS;
                cp_async16(dst + c * 16, src + c * 16);
            }
            cp_async_commit();
            if (tid < 64) {
                wq[nxt][skk4 * NOUT + so] = wpre1;
                if (i + 2 < CIN)
                    wpre1 = *reinterpret_cast<const float4*>(
                        wsrc + (i + 2) * K_TAPS);
            }
        }

        // ---- compute current channel: 8 groups of 4 taps ----
#pragma unroll
        for (int kk4 = 0; kk4 < K_TAPS / 4; ++kk4) {
            float4 wv[NOUT];
#pragma unroll
            for (int o = 0; o < NOUT; ++o)
                wv[o] = wq[cur][kk4 * NOUT + o];     // broadcast LDS.128

#pragma unroll
            for (int s = 0; s < 4; ++s) {
                const int off = SK[4 * kk4 + s] + LOWPAD;
                float2 xv[NPAIR];
#pragma unroll
                for (int p = 0; p < NPAIR; ++p)
                    xv[p] = win[cur][tid + THREADS * p + off];
#pragma unroll
                for (int o = 0; o < NOUT; ++o) {
                    const float ws = (s == 0) ? wv[o].x :
                                     (s == 1) ? wv[o].y :
                                     (s == 2) ? wv[o].z : wv[o].w;
                    float2 wd = make_float2(ws, ws);  // ALU dup
#pragma unroll
                    for (int p = 0; p < NPAIR; ++p)
                        acc[o][p] = ffma2(wd, xv[p], acc[o][p]);
                }
            }
        }

        if (more) cp_async_wait_all();
        __syncthreads();     // one barrier per channel
    }

    // ---- store: lanes are (b0, b1) at the same (o, l) ----
    const int b0 = bp * 2;
#pragma unroll
    for (int o = 0; o < NOUT; ++o) {
        float* q0 = out + ((size_t)(b0)     * COUT + o0 + o) * LEN + l0;
        float* q1 = out + ((size_t)(b0 + 1) * COUT + o0 + o) * LEN + l0;
#pragma unroll
        for (int p = 0; p < NPAIR; ++p) {
            int l = tid + THREADS * p;
            q0[l] = acc[o][p].x;
            q1[l] = acc[o][p].y;
        }
    }
}

extern "C" void kernel_launch(void* const* d_in, const int* in_sizes, int n_in,
                              void* d_out, int out_size) {
    const float* x = (const float*)d_in[0];   // [16,64,4096]
    const float* w = (const float*)d_in[1];   // [64,64,32]
    float* out = (float*)d_out;               // [16,64,4096]

    int total = NBP * CIN * PADLEN;
    interleave_kernel<<<(total + 255) / 256, 256>>>(x);

    dim3 grid(LEN / LTILE, COUT / NOUT, NBP);  // (8, 8, 8) = 512 blocks
    sk_conv_kernel<<<grid, THREADS>>>(w, out);
}

// round 10
// speedup vs baseline: 2.3988x; 2.3988x over previous
#include <cuda_runtime.h>
#include <cuda_bf16.h>
#include <cstdint>

// SparseConv1D as 32 shifted GEMMs on tensor cores via mma.sync (bf16 3-split).
// out[b,o,l] = sum_i sum_k w[o,i,k] * x[b,i,l+d_k], zero pad out-of-range.
// Valid on plain sm_103 target: mma.sync/ldmatrix/cp.async only (no tcgen05).

#define LEN 4096
#define CIN 64
#define COUT 64
#define BATCH 16
#define K_TAPS 32
#define PADLEN 4864          // 512 low pad + 4096 + 256 high pad
#define THREADS 512
#define WROWS 1280           // window rows: 512 tile + 768 pad
#define RSTRIDE 144          // smem row stride bytes (conflict-free ldmatrix)
#define SMEM_BYTES (WROWS * RSTRIDE)   // 184320

// x transposed: [b][pos_pad][64ch] bf16, hi/lo split
__device__ __align__(16) __nv_bfloat16 g_xhi[(size_t)BATCH * PADLEN * CIN];
__device__ __align__(16) __nv_bfloat16 g_xlo[(size_t)BATCH * PADLEN * CIN];
// weights fragment-packed: [tap][var][ktile4][ntile8][lane32] uint2 (4 bf16)
__device__ __align__(16) uint2 g_wf[K_TAPS * 2 * 4 * 8 * 32];

__constant__ int c_sk[K_TAPS] = {
    -512,-256,-128,-96,-64,-48,-32,-24,-16,-12,-8,-6,-4,-3,-2,-1,
     0,1,2,3,4,6,8,12,16,24,32,48,64,96,128,256
};

__device__ __forceinline__ unsigned smem_u32(const void* p) {
    unsigned a;
    asm("{ .reg .u64 t; cvta.to.shared.u64 t, %1; cvt.u32.u64 %0, t; }"
        : "=r"(a) : "l"(p));
    return a;
}
__device__ __forceinline__ void cp16(unsigned d, const void* s) {
    asm volatile("cp.async.cg.shared.global [%0], [%1], 16;" :: "r"(d), "l"(s));
}
__device__ __forceinline__ void cpc()  { asm volatile("cp.async.commit_group;"); }
__device__ __forceinline__ void cpw0() { asm volatile("cp.async.wait_group 0;"); }

__device__ __forceinline__ void ldmA(unsigned* r, unsigned addr) {
    asm volatile("ldmatrix.sync.aligned.m8n8.x4.shared.b16 {%0,%1,%2,%3}, [%4];"
        : "=r"(r[0]), "=r"(r[1]), "=r"(r[2]), "=r"(r[3]) : "r"(addr));
}
__device__ __forceinline__ void mma16816(float* d, const unsigned* a, uint2 b) {
    asm volatile(
        "mma.sync.aligned.m16n8k16.row.col.f32.bf16.bf16.f32 "
        "{%0,%1,%2,%3}, {%4,%5,%6,%7}, {%8,%9}, {%0,%1,%2,%3};"
        : "+f"(d[0]), "+f"(d[1]), "+f"(d[2]), "+f"(d[3])
        : "r"(a[0]), "r"(a[1]), "r"(a[2]), "r"(a[3]), "r"(b.x), "r"(b.y));
}
__device__ __forceinline__ unsigned pk(__nv_bfloat16 a, __nv_bfloat16 b) {
    __nv_bfloat162 t(a, b);
    return *reinterpret_cast<unsigned*>(&t);
}

// ---- prepass: transpose x -> [b][pos][ch] bf16 hi/lo, padded --------------
__global__ __launch_bounds__(512) void prep_x(const float* __restrict__ x) {
    __shared__ float tile[64][65];
    const int p0 = blockIdx.x * 64, b = blockIdx.y, tid = threadIdx.x;
#pragma unroll
    for (int it = 0; it < 8; ++it) {
        int e = tid + it * 512;                 // 0..4095
        int ch = e >> 6, pos = e & 63;
        tile[ch][pos] = x[((size_t)b * CIN + ch) * LEN + p0 + pos];
    }
    __syncthreads();
    const int j = tid & 7, pp = tid >> 3;       // 8 ch-groups x 64 positions
    __nv_bfloat16 h[8], lo[8];
#pragma unroll
    for (int c = 0; c < 8; ++c) {
        float v = tile[j * 8 + c][pp];
        h[c]  = __float2bfloat16(v);
        lo[c] = __float2bfloat16(v - __bfloat162float(h[c]));
    }
    size_t off = ((size_t)b * PADLEN + 512 + p0 + pp) * CIN + j * 8;
    *reinterpret_cast<uint4*>(g_xhi + off) =
        make_uint4(pk(h[0],h[1]), pk(h[2],h[3]), pk(h[4],h[5]), pk(h[6],h[7]));
    *reinterpret_cast<uint4*>(g_xlo + off) =
        make_uint4(pk(lo[0],lo[1]), pk(lo[2],lo[3]), pk(lo[4],lo[5]), pk(lo[6],lo[7]));
}

__global__ void prep_zero() {
    int idx = blockIdx.x * blockDim.x + threadIdx.x;  // BATCH*768*8
    if (idx >= BATCH * 768 * 8) return;
    int j = idx & 7, r = (idx >> 3) % 768, b = idx / (768 * 8);
    int pp = (r < 512) ? r : r + 4096;
    size_t off = ((size_t)b * PADLEN + pp) * CIN + j * 8;
    uint4 z = make_uint4(0, 0, 0, 0);
    *reinterpret_cast<uint4*>(g_xhi + off) = z;
    *reinterpret_cast<uint4*>(g_xlo + off) = z;
}

// ---- prepass: weights in B-fragment order ---------------------------------
// b0 = {B[k][n], B[k+1][n]}, b1 = {B[k+8][n], B[k+9][n]}; n=ntile*8+lane/4,
// k=ktile*16+(lane%4)*2; B[k][n] = w_var[o=n][ch=k].
__global__ void prep_w(const float* __restrict__ w) {
    int idx = blockIdx.x * blockDim.x + threadIdx.x;  // 32*4*8*32
    if (idx >= K_TAPS * 4 * 8 * 32) return;
    int lane = idx & 31, nt = (idx >> 5) & 7, kt = (idx >> 8) & 3, t = idx >> 10;
    int n = nt * 8 + (lane >> 2);
    int k = kt * 16 + (lane & 3) * 2;
    float v0 = w[((size_t)n * CIN + k)     * K_TAPS + t];
    float v1 = w[((size_t)n * CIN + k + 1) * K_TAPS + t];
    float v8 = w[((size_t)n * CIN + k + 8) * K_TAPS + t];
    float v9 = w[((size_t)n * CIN + k + 9) * K_TAPS + t];
    __nv_bfloat16 h0 = __float2bfloat16(v0), h1 = __float2bfloat16(v1);
    __nv_bfloat16 h8 = __float2bfloat16(v8), h9 = __float2bfloat16(v9);
    size_t base = ((size_t)(t * 2) * 4 + kt) * 256 + nt * 32 + lane;
    g_wf[base] = make_uint2(pk(h0, h1), pk(h8, h9));
    __nv_bfloat16 l0 = __float2bfloat16(v0 - __bfloat162float(h0));
    __nv_bfloat16 l1 = __float2bfloat16(v1 - __bfloat162float(h1));
    __nv_bfloat16 l8 = __float2bfloat16(v8 - __bfloat162float(h8));
    __nv_bfloat16 l9 = __float2bfloat16(v9 - __bfloat162float(h9));
    g_wf[base + 4 * 256] = make_uint2(pk(l0, l1), pk(l8, l9));  // var=1 slot
}

// ---- main kernel -----------------------------------------------------------
__global__ __launch_bounds__(THREADS, 1)
void conv_mma(float* __restrict__ out) {
    extern __shared__ __align__(16) char smem[];
    const unsigned win_s = smem_u32(smem);
    const int tid = threadIdx.x, wid = tid >> 5, lane = tid & 31;
    const int st = blockIdx.x, b = blockIdx.y;
    const int P0 = st * 512;

    float acc[2][8][4];
#pragma unroll
    for (int mt = 0; mt < 2; ++mt)
#pragma unroll
        for (int n = 0; n < 8; ++n)
#pragma unroll
            for (int q = 0; q < 4; ++q) acc[mt][n][q] = 0.f;

    const int lrow = lane & 15;            // ldmatrix row within m16 tile
    const int lcolb = ((lane >> 4) * 8) * 2;  // byte offset of k-half

    for (int pass = 0; pass < 2; ++pass) {
        __syncthreads();                   // window reuse: pass-0 reads done
        const __nv_bfloat16* gx = pass ? g_xlo : g_xhi;
        const __nv_bfloat16* base = gx + ((size_t)b * PADLEN + P0) * CIN;
#pragma unroll
        for (int it = 0; it < (WROWS * 8) / THREADS; ++it) {
            int c = tid + it * THREADS;
            int row = c >> 3, ch = c & 7;
            cp16(win_s + row * RSTRIDE + ch * 16, base + row * CIN + ch * 8);
        }
        cpc(); cpw0();
        __syncthreads();

        const int nv = pass ? 1 : 2;       // xhi: w_hi+w_lo ; xlo: w_hi
        for (int t = 0; t < K_TAPS; ++t) {
            const int rowb = wid * 32 + c_sk[t] + 512;
#pragma unroll
            for (int k = 0; k < 4; ++k) {
                unsigned a[2][4];
#pragma unroll
                for (int mt = 0; mt < 2; ++mt)
                    ldmA(a[mt], win_s + (rowb + mt * 16 + lrow) * RSTRIDE
                                      + k * 32 + lcolb);
                for (int v = 0; v < nv; ++v) {
                    const uint2* bp =
                        g_wf + ((size_t)(t * 2 + v) * 4 + k) * 256 + lane;
                    uint2 bf[8];
#pragma unroll
                    for (int n = 0; n < 8; ++n) bf[n] = bp[n * 32];
#pragma unroll
                    for (int mt = 0; mt < 2; ++mt)
#pragma unroll
                        for (int n = 0; n < 8; ++n)
                            mma16816(acc[mt][n], a[mt], bf[n]);
                }
            }
        }
    }

    // ---- store D fragments: rows=positions, cols=outputs ----
    const int g = lane >> 2, c0 = (lane & 3) * 2;
#pragma unroll
    for (int mt = 0; mt < 2; ++mt) {
        const int pos = P0 + wid * 32 + mt * 16 + g;
#pragma unroll
        for (int n = 0; n < 8; ++n) {
            const int o = n * 8 + c0;
            float* q0 = out + ((size_t)b * COUT + o) * LEN;
            float* q1 = out + ((size_t)b * COUT + o + 1) * LEN;
            q0[pos]     = acc[mt][n][0];
            q1[pos]     = acc[mt][n][1];
            q0[pos + 8] = acc[mt][n][2];
            q1[pos + 8] = acc[mt][n][3];
        }
    }
}

extern "C" void kernel_launch(void* const* d_in, const int* in_sizes, int n_in,
                              void* d_out, int out_size) {
    const float* x = (const float*)d_in[0];   // [16,64,4096]
    const float* w = (const float*)d_in[1];   // [64,64,32]
    float* out = (float*)d_out;               // [16,64,4096]

    prep_x<<<dim3(LEN / 64, BATCH), 512>>>(x);
    prep_zero<<<(BATCH * 768 * 8 + 255) / 256, 256>>>();
    prep_w<<<(K_TAPS * 4 * 8 * 32 + 255) / 256, 256>>>(w);

    cudaFuncSetAttribute(conv_mma, cudaFuncAttributeMaxDynamicSharedMemorySize,
                         SMEM_BYTES);
    conv_mma<<<dim3(8, BATCH), THREADS, SMEM_BYTES>>>(out);
}

// round 11
// speedup vs baseline: 2.5425x; 1.0599x over previous
#include <cuda_runtime.h>
#include <cuda_bf16.h>
#include <cstdint>

// SparseConv1D as 32 shifted GEMMs on tensor cores via mma.sync (bf16 3-split),
// software-pipelined: B-fragment and A-fragment double buffering across steps.

#define LEN 4096
#define CIN 64
#define COUT 64
#define BATCH 16
#define K_TAPS 32
#define PADLEN 4864
#define THREADS 512
#define WROWS 1280
#define RSTRIDE 144
#define SMEM_BYTES (WROWS * RSTRIDE)
#define NSTEP 128                       // 32 taps x 4 k-tiles

__device__ __align__(16) __nv_bfloat16 g_xhi[(size_t)BATCH * PADLEN * CIN];
__device__ __align__(16) __nv_bfloat16 g_xlo[(size_t)BATCH * PADLEN * CIN];
__device__ __align__(16) uint2 g_wf[K_TAPS * 2 * 4 * 8 * 32];

__constant__ int c_sk[K_TAPS] = {
    -512,-256,-128,-96,-64,-48,-32,-24,-16,-12,-8,-6,-4,-3,-2,-1,
     0,1,2,3,4,6,8,12,16,24,32,48,64,96,128,256
};

__device__ __forceinline__ unsigned smem_u32(const void* p) {
    unsigned a;
    asm("{ .reg .u64 t; cvta.to.shared.u64 t, %1; cvt.u32.u64 %0, t; }"
        : "=r"(a) : "l"(p));
    return a;
}
__device__ __forceinline__ void cp16(unsigned d, const void* s) {
    asm volatile("cp.async.cg.shared.global [%0], [%1], 16;" :: "r"(d), "l"(s));
}
__device__ __forceinline__ void cpc()  { asm volatile("cp.async.commit_group;"); }
__device__ __forceinline__ void cpw0() { asm volatile("cp.async.wait_group 0;"); }
__device__ __forceinline__ void ldmA(unsigned* r, unsigned addr) {
    asm volatile("ldmatrix.sync.aligned.m8n8.x4.shared.b16 {%0,%1,%2,%3}, [%4];"
        : "=r"(r[0]), "=r"(r[1]), "=r"(r[2]), "=r"(r[3]) : "r"(addr));
}
__device__ __forceinline__ void mma16816(float* d, const unsigned* a, uint2 b) {
    asm volatile(
        "mma.sync.aligned.m16n8k16.row.col.f32.bf16.bf16.f32 "
        "{%0,%1,%2,%3}, {%4,%5,%6,%7}, {%8,%9}, {%0,%1,%2,%3};"
        : "+f"(d[0]), "+f"(d[1]), "+f"(d[2]), "+f"(d[3])
        : "r"(a[0]), "r"(a[1]), "r"(a[2]), "r"(a[3]), "r"(b.x), "r"(b.y));
}
__device__ __forceinline__ unsigned pk(__nv_bfloat16 a, __nv_bfloat16 b) {
    __nv_bfloat162 t(a, b);
    return *reinterpret_cast<unsigned*>(&t);
}

// ---- prepasses (unchanged from round 10) ----
__global__ __launch_bounds__(512) void prep_x(const float* __restrict__ x) {
    __shared__ float tile[64][65];
    const int p0 = blockIdx.x * 64, b = blockIdx.y, tid = threadIdx.x;
#pragma unroll
    for (int it = 0; it < 8; ++it) {
        int e = tid + it * 512;
        int ch = e >> 6, pos = e & 63;
        tile[ch][pos] = x[((size_t)b * CIN + ch) * LEN + p0 + pos];
    }
    __syncthreads();
    const int j = tid & 7, pp = tid >> 3;
    __nv_bfloat16 h[8], lo[8];
#pragma unroll
    for (int c = 0; c < 8; ++c) {
        float v = tile[j * 8 + c][pp];
        h[c]  = __float2bfloat16(v);
        lo[c] = __float2bfloat16(v - __bfloat162float(h[c]));
    }
    size_t off = ((size_t)b * PADLEN + 512 + p0 + pp) * CIN + j * 8;
    *reinterpret_cast<uint4*>(g_xhi + off) =
        make_uint4(pk(h[0],h[1]), pk(h[2],h[3]), pk(h[4],h[5]), pk(h[6],h[7]));
    *reinterpret_cast<uint4*>(g_xlo + off) =
        make_uint4(pk(lo[0],lo[1]), pk(lo[2],lo[3]), pk(lo[4],lo[5]), pk(lo[6],lo[7]));
}
__global__ void prep_zero() {
    int idx = blockIdx.x * blockDim.x + threadIdx.x;
    if (idx >= BATCH * 768 * 8) return;
    int j = idx & 7, r = (idx >> 3) % 768, b = idx / (768 * 8);
    int pp = (r < 512) ? r : r + 4096;
    size_t off = ((size_t)b * PADLEN + pp) * CIN + j * 8;
    uint4 z = make_uint4(0, 0, 0, 0);
    *reinterpret_cast<uint4*>(g_xhi + off) = z;
    *reinterpret_cast<uint4*>(g_xlo + off) = z;
}
__global__ void prep_w(const float* __restrict__ w) {
    int idx = blockIdx.x * blockDim.x + threadIdx.x;
    if (idx >= K_TAPS * 4 * 8 * 32) return;
    int lane = idx & 31, nt = (idx >> 5) & 7, kt = (idx >> 8) & 3, t = idx >> 10;
    int n = nt * 8 + (lane >> 2);
    int k = kt * 16 + (lane & 3) * 2;
    float v0 = w[((size_t)n * CIN + k)     * K_TAPS + t];
    float v1 = w[((size_t)n * CIN + k + 1) * K_TAPS + t];
    float v8 = w[((size_t)n * CIN + k + 8) * K_TAPS + t];
    float v9 = w[((size_t)n * CIN + k + 9) * K_TAPS + t];
    __nv_bfloat16 h0 = __float2bfloat16(v0), h1 = __float2bfloat16(v1);
    __nv_bfloat16 h8 = __float2bfloat16(v8), h9 = __float2bfloat16(v9);
    size_t base = ((size_t)(t * 2) * 4 + kt) * 256 + nt * 32 + lane;
    g_wf[base] = make_uint2(pk(h0, h1), pk(h8, h9));
    __nv_bfloat16 l0 = __float2bfloat16(v0 - __bfloat162float(h0));
    __nv_bfloat16 l1 = __float2bfloat16(v1 - __bfloat162float(h1));
    __nv_bfloat16 l8 = __float2bfloat16(v8 - __bfloat162float(h8));
    __nv_bfloat16 l9 = __float2bfloat16(v9 - __bfloat162float(h9));
    g_wf[base + 4 * 256] = make_uint2(pk(l0, l1), pk(l8, l9));
}

// ---- pipelined main kernel ----
struct Ctx {
    unsigned win_s;
    int wid, lrow, lcolb, lane;
};

__device__ __forceinline__ void ldaS(const Ctx& c, unsigned (&a)[2][4], int s) {
    const int t = s >> 2, k = s & 3;
    const int rowb = c.wid * 32 + c_sk[t] + 512;
    const unsigned base =
        c.win_s + (unsigned)((rowb + c.lrow) * RSTRIDE + k * 32 + c.lcolb);
    ldmA(a[0], base);
    ldmA(a[1], base + 16 * RSTRIDE);
}

template <int NSUB>
__device__ __forceinline__ void loadB(const Ctx& c, uint2 (&b)[4], int s, int u) {
    const int t = s >> 2, k = s & 3;
    const int v = (NSUB == 4) ? (u >> 1) : 0;
    const int h = u & 1;
    const uint2* bp =
        g_wf + (((size_t)(t * 2 + v) * 4 + k) * 256) + h * 128 + c.lane;
#pragma unroll
    for (int i = 0; i < 4; ++i) b[i] = bp[i * 32];
}

template <int NSUB>
__device__ __forceinline__ void step(const Ctx& c, int s,
                                     unsigned (&aC)[2][4], unsigned (&aN)[2][4],
                                     uint2 (&bf)[2][4], float (&acc)[2][8][4]) {
#pragma unroll
    for (int u = 0; u < NSUB; ++u) {
        uint2 (&cur)[4] = bf[u & 1];
        uint2 (&nxt)[4] = bf[(u + 1) & 1];
        if (u == 0 && s + 1 < NSTEP) ldaS(c, aN, s + 1);   // A for next step
        if (u + 1 < NSUB) loadB<NSUB>(c, nxt, s, u + 1);   // B for next sub
        else if (s + 1 < NSTEP) loadB<NSUB>(c, nxt, s + 1, 0);
        const int h = u & 1;
#pragma unroll
        for (int i = 0; i < 4; ++i)
#pragma unroll
            for (int mt = 0; mt < 2; ++mt)
                mma16816(acc[mt][h * 4 + i], aC[mt], cur[i]);
    }
}

__global__ __launch_bounds__(THREADS, 1)
void conv_mma(float* __restrict__ out) {
    extern __shared__ __align__(16) char smem[];
    const int tid = threadIdx.x, wid = tid >> 5, lane = tid & 31;
    const int st = blockIdx.x, b = blockIdx.y;
    const int P0 = st * 512;

    Ctx c;
    c.win_s = smem_u32(smem);
    c.wid = wid;
    c.lane = lane;
    c.lrow = lane & 15;
    c.lcolb = ((lane >> 4) * 8) * 2;

    float acc[2][8][4];
#pragma unroll
    for (int mt = 0; mt < 2; ++mt)
#pragma unroll
        for (int n = 0; n < 8; ++n)
#pragma unroll
            for (int q = 0; q < 4; ++q) acc[mt][n][q] = 0.f;

    unsigned aA[2][4], aB[2][4];
    uint2 bf[2][4];

    for (int pass = 0; pass < 2; ++pass) {
        __syncthreads();
        const __nv_bfloat16* gx = pass ? g_xlo : g_xhi;
        const __nv_bfloat16* base = gx + ((size_t)b * PADLEN + P0) * CIN;
#pragma unroll
        for (int it = 0; it < (WROWS * 8) / THREADS; ++it) {
            int cc = tid + it * THREADS;
            int row = cc >> 3, ch = cc & 7;
            cp16(c.win_s + row * RSTRIDE + ch * 16, base + row * CIN + ch * 8);
        }
        cpc(); cpw0();
        __syncthreads();

        ldaS(c, aA, 0);
        if (pass == 0) {
            loadB<4>(c, bf[0], 0, 0);
            for (int s = 0; s < NSTEP; s += 2) {
                step<4>(c, s,     aA, aB, bf, acc);
                step<4>(c, s + 1, aB, aA, bf, acc);
            }
        } else {
            loadB<2>(c, bf[0], 0, 0);
            for (int s = 0; s < NSTEP; s += 2) {
                step<2>(c, s,     aA, aB, bf, acc);
                step<2>(c, s + 1, aB, aA, bf, acc);
            }
        }
    }

    // ---- store D fragments ----
    const int g = lane >> 2, c0 = (lane & 3) * 2;
#pragma unroll
    for (int mt = 0; mt < 2; ++mt) {
        const int pos = P0 + wid * 32 + mt * 16 + g;
#pragma unroll
        for (int n = 0; n < 8; ++n) {
            const int o = n * 8 + c0;
            float* q0 = out + ((size_t)b * COUT + o) * LEN;
            float* q1 = out + ((size_t)b * COUT + o + 1) * LEN;
            q0[pos]     = acc[mt][n][0];
            q1[pos]     = acc[mt][n][1];
            q0[pos + 8] = acc[mt][n][2];
            q1[pos + 8] = acc[mt][n][3];
        }
    }
}

extern "C" void kernel_launch(void* const* d_in, const int* in_sizes, int n_in,
                              void* d_out, int out_size) {
    const float* x = (const float*)d_in[0];
    const float* w = (const float*)d_in[1];
    float* out = (float*)d_out;

    prep_x<<<dim3(LEN / 64, BATCH), 512>>>(x);
    prep_zero<<<(BATCH * 768 * 8 + 255) / 256, 256>>>();
    prep_w<<<(K_TAPS * 4 * 8 * 32 + 255) / 256, 256>>>(w);

    cudaFuncSetAttribute(conv_mma, cudaFuncAttributeMaxDynamicSharedMemorySize,
                         SMEM_BYTES);
    conv_mma<<<dim3(8, BATCH), THREADS, SMEM_BYTES>>>(out);
}

// round 12
// speedup vs baseline: 2.8209x; 1.1095x over previous
#include <cuda_runtime.h>
#include <cuda_bf16.h>
#include <cstdint>

// SparseConv1D as 32 shifted GEMMs via mma.sync bf16 3-split.
// R12: B fragments staged per-tap into smem with cp.async double buffering
// (kills the per-substep L2-latency exposure that starved the tensor pipe).

#define LEN 4096
#define CIN 64
#define COUT 64
#define BATCH 16
#define K_TAPS 32
#define PADLEN 4864
#define THREADS 512
#define WROWS 1280
#define RSTRIDE 144
#define WINBYTES (WROWS * RSTRIDE)          // 184320
#define BSM_BYTES (2 * 16384)               // double-buffered tap B
#define SMEM_BYTES (WINBYTES + BSM_BYTES)   // 217088

__device__ __align__(16) __nv_bfloat16 g_xhi[(size_t)BATCH * PADLEN * CIN];
__device__ __align__(16) __nv_bfloat16 g_xlo[(size_t)BATCH * PADLEN * CIN];
__device__ __align__(16) uint2 g_wf[K_TAPS * 2 * 4 * 8 * 32];   // [tap][v][k][..]

__constant__ int c_sk[K_TAPS] = {
    -512,-256,-128,-96,-64,-48,-32,-24,-16,-12,-8,-6,-4,-3,-2,-1,
     0,1,2,3,4,6,8,12,16,24,32,48,64,96,128,256
};

__device__ __forceinline__ unsigned smem_u32(const void* p) {
    unsigned a;
    asm("{ .reg .u64 t; cvta.to.shared.u64 t, %1; cvt.u32.u64 %0, t; }"
        : "=r"(a) : "l"(p));
    return a;
}
__device__ __forceinline__ void cp16(unsigned d, const void* s) {
    asm volatile("cp.async.cg.shared.global [%0], [%1], 16;" :: "r"(d), "l"(s));
}
__device__ __forceinline__ void cpc()  { asm volatile("cp.async.commit_group;"); }
__device__ __forceinline__ void cpw0() { asm volatile("cp.async.wait_group 0;"); }
__device__ __forceinline__ void ldmA(unsigned* r, unsigned addr) {
    asm volatile("ldmatrix.sync.aligned.m8n8.x4.shared.b16 {%0,%1,%2,%3}, [%4];"
        : "=r"(r[0]), "=r"(r[1]), "=r"(r[2]), "=r"(r[3]) : "r"(addr));
}
__device__ __forceinline__ void mma16816(float* d, const unsigned* a, uint2 b) {
    asm volatile(
        "mma.sync.aligned.m16n8k16.row.col.f32.bf16.bf16.f32 "
        "{%0,%1,%2,%3}, {%4,%5,%6,%7}, {%8,%9}, {%0,%1,%2,%3};"
        : "+f"(d[0]), "+f"(d[1]), "+f"(d[2]), "+f"(d[3])
        : "r"(a[0]), "r"(a[1]), "r"(a[2]), "r"(a[3]), "r"(b.x), "r"(b.y));
}
__device__ __forceinline__ unsigned pk(__nv_bfloat16 a, __nv_bfloat16 b) {
    __nv_bfloat162 t(a, b);
    return *reinterpret_cast<unsigned*>(&t);
}

// ---- prepasses (unchanged) ----
__global__ __launch_bounds__(512) void prep_x(const float* __restrict__ x) {
    __shared__ float tile[64][65];
    const int p0 = blockIdx.x * 64, b = blockIdx.y, tid = threadIdx.x;
#pragma unroll
    for (int it = 0; it < 8; ++it) {
        int e = tid + it * 512;
        int ch = e >> 6, pos = e & 63;
        tile[ch][pos] = x[((size_t)b * CIN + ch) * LEN + p0 + pos];
    }
    __syncthreads();
    const int j = tid & 7, pp = tid >> 3;
    __nv_bfloat16 h[8], lo[8];
#pragma unroll
    for (int c = 0; c < 8; ++c) {
        float v = tile[j * 8 + c][pp];
        h[c]  = __float2bfloat16(v);
        lo[c] = __float2bfloat16(v - __bfloat162float(h[c]));
    }
    size_t off = ((size_t)b * PADLEN + 512 + p0 + pp) * CIN + j * 8;
    *reinterpret_cast<uint4*>(g_xhi + off) =
        make_uint4(pk(h[0],h[1]), pk(h[2],h[3]), pk(h[4],h[5]), pk(h[6],h[7]));
    *reinterpret_cast<uint4*>(g_xlo + off) =
        make_uint4(pk(lo[0],lo[1]), pk(lo[2],lo[3]), pk(lo[4],lo[5]), pk(lo[6],lo[7]));
}
__global__ void prep_zero() {
    int idx = blockIdx.x * blockDim.x + threadIdx.x;
    if (idx >= BATCH * 768 * 8) return;
    int j = idx & 7, r = (idx >> 3) % 768, b = idx / (768 * 8);
    int pp = (r < 512) ? r : r + 4096;
    size_t off = ((size_t)b * PADLEN + pp) * CIN + j * 8;
    uint4 z = make_uint4(0, 0, 0, 0);
    *reinterpret_cast<uint4*>(g_xhi + off) = z;
    *reinterpret_cast<uint4*>(g_xlo + off) = z;
}
__global__ void prep_w(const float* __restrict__ w) {
    int idx = blockIdx.x * blockDim.x + threadIdx.x;
    if (idx >= K_TAPS * 4 * 8 * 32) return;
    int lane = idx & 31, nt = (idx >> 5) & 7, kt = (idx >> 8) & 3, t = idx >> 10;
    int n = nt * 8 + (lane >> 2);
    int k = kt * 16 + (lane & 3) * 2;
    float v0 = w[((size_t)n * CIN + k)     * K_TAPS + t];
    float v1 = w[((size_t)n * CIN + k + 1) * K_TAPS + t];
    float v8 = w[((size_t)n * CIN + k + 8) * K_TAPS + t];
    float v9 = w[((size_t)n * CIN + k + 9) * K_TAPS + t];
    __nv_bfloat16 h0 = __float2bfloat16(v0), h1 = __float2bfloat16(v1);
    __nv_bfloat16 h8 = __float2bfloat16(v8), h9 = __float2bfloat16(v9);
    size_t base = ((size_t)(t * 2) * 4 + kt) * 256 + nt * 32 + lane;
    g_wf[base] = make_uint2(pk(h0, h1), pk(h8, h9));
    __nv_bfloat16 l0 = __float2bfloat16(v0 - __bfloat162float(h0));
    __nv_bfloat16 l1 = __float2bfloat16(v1 - __bfloat162float(h1));
    __nv_bfloat16 l8 = __float2bfloat16(v8 - __bfloat162float(h8));
    __nv_bfloat16 l9 = __float2bfloat16(v9 - __bfloat162float(h9));
    g_wf[base + 4 * 256] = make_uint2(pk(l0, l1), pk(l8, l9));
}

// ---- main kernel ----
struct Ctx {
    unsigned win_s, bsm_s;
    const uint2* bsm;
    int wid, lane, lrow, lcolb, tid;
};

__device__ __forceinline__ void ldaS(const Ctx& c, unsigned (&a)[2][4], int s) {
    const int rowb = c.wid * 32 + c_sk[s >> 2] + 512;
    const int k = s & 3;
    const unsigned base =
        c.win_s + (unsigned)((rowb + c.lrow) * RSTRIDE + k * 32 + c.lcolb);
    ldmA(a[0], base);
    ldmA(a[1], base + 16 * RSTRIDE);
}
__device__ __forceinline__ void loadBsm(const Ctx& c, const uint2* bb,
                                        uint2 (&b)[4], int v, int k, int h) {
    const uint2* p = bb + (v * 4 + k) * 256 + h * 128 + c.lane;
#pragma unroll
    for (int i = 0; i < 4; ++i) b[i] = p[i * 32];
}

template <int NSUB>   // 4 for xhi pass (w_hi+w_lo), 2 for xlo pass (w_hi)
__device__ __forceinline__ void run_pass(const Ctx& c,
                                         const __nv_bfloat16* base,
                                         float (&acc)[2][8][4]) {
    // fill window
#pragma unroll
    for (int it = 0; it < (WROWS * 8) / THREADS; ++it) {
        int cc = c.tid + it * THREADS;
        int row = cc >> 3, ch = cc & 7;
        cp16(c.win_s + row * RSTRIDE + ch * 16, base + row * CIN + ch * 8);
    }
    // B for tap 0 into slot 0 (nv*8KB contiguous per tap in g_wf)
    const char* wsrc = (const char*)g_wf;
#pragma unroll
    for (int q = 0; q < NSUB / 2; ++q) {
        int cc = c.tid + q * THREADS;
        cp16(c.bsm_s + cc * 16, wsrc + cc * 16);
    }
    cpc(); cpw0();
    __syncthreads();

    unsigned a[2][2][4];
    uint2 bf[2][4];
    ldaS(c, a[0], 0);
    loadBsm(c, c.bsm, bf[0], 0, 0, 0);

    for (int t = 0; t < K_TAPS; ++t) {
        const int buf = t & 1;
        const uint2* bb = c.bsm + buf * 2048;
        if (t + 1 < K_TAPS) {     // async-copy next tap's B into other slot
            const char* src = wsrc + (size_t)(t + 1) * 16384;
            const unsigned dst = c.bsm_s + (buf ^ 1) * 16384;
#pragma unroll
            for (int q = 0; q < NSUB / 2; ++q) {
                int cc = c.tid + q * THREADS;
                cp16(dst + cc * 16, src + cc * 16);
            }
            cpc();
        }
#pragma unroll
        for (int k = 0; k < 4; ++k) {
            const int s = t * 4 + k;
            unsigned (&aC)[2][4] = a[k & 1];
            unsigned (&aN)[2][4] = a[(k + 1) & 1];
#pragma unroll
            for (int u = 0; u < NSUB; ++u) {
                const int m = k * NSUB + u;
                uint2 (&cur)[4] = bf[m & 1];
                uint2 (&nxt)[4] = bf[(m + 1) & 1];
                if (u == 0 && s + 1 < 4 * K_TAPS) ldaS(c, aN, s + 1);
                if (m + 1 < 4 * NSUB) {      // next B sub within this tap
                    const int m2 = m + 1;
                    const int k2 = m2 / NSUB, u2 = m2 % NSUB;
                    loadBsm(c, bb, nxt, (NSUB == 4) ? (u2 >> 1) : 0, k2, u2 & 1);
                }
                const int h = u & 1;
#pragma unroll
                for (int i = 0; i < 4; ++i)
#pragma unroll
                    for (int mt = 0; mt < 2; ++mt)
                        mma16816(acc[mt][h * 4 + i], aC[mt], cur[i]);
            }
        }
        cpw0();
        __syncthreads();
        if (t + 1 < K_TAPS)
            loadBsm(c, c.bsm + (buf ^ 1) * 2048, bf[0], 0, 0, 0);
    }
}

__global__ __launch_bounds__(THREADS, 1)
void conv_mma(float* __restrict__ out) {
    extern __shared__ __align__(16) char smem[];
    const int tid = threadIdx.x, wid = tid >> 5, lane = tid & 31;
    const int st = blockIdx.x, b = blockIdx.y;
    const int P0 = st * 512;

    Ctx c;
    c.win_s = smem_u32(smem);
    c.bsm_s = c.win_s + WINBYTES;
    c.bsm   = reinterpret_cast<const uint2*>(smem + WINBYTES);
    c.wid = wid; c.lane = lane; c.tid = tid;
    c.lrow = lane & 15;
    c.lcolb = ((lane >> 4) * 8) * 2;

    float acc[2][8][4];
#pragma unroll
    for (int mt = 0; mt < 2; ++mt)
#pragma unroll
        for (int n = 0; n < 8; ++n)
#pragma unroll
            for (int q = 0; q < 4; ++q) acc[mt][n][q] = 0.f;

    run_pass<4>(c, g_xhi + ((size_t)b * PADLEN + P0) * CIN, acc);
    __syncthreads();
    run_pass<2>(c, g_xlo + ((size_t)b * PADLEN + P0) * CIN, acc);

    // ---- store D fragments ----
    const int g = lane >> 2, c0 = (lane & 3) * 2;
#pragma unroll
    for (int mt = 0; mt < 2; ++mt) {
        const int pos = P0 + wid * 32 + mt * 16 + g;
#pragma unroll
        for (int n = 0; n < 8; ++n) {
            const int o = n * 8 + c0;
            float* q0 = out + ((size_t)b * COUT + o) * LEN;
            float* q1 = out + ((size_t)b * COUT + o + 1) * LEN;
            q0[pos]     = acc[mt][n][0];
            q1[pos]     = acc[mt][n][1];
            q0[pos + 8] = acc[mt][n][2];
            q1[pos + 8] = acc[mt][n][3];
        }
    }
}

extern "C" void kernel_launch(void* const* d_in, const int* in_sizes, int n_in,
                              void* d_out, int out_size) {
    const float* x = (const float*)d_in[0];
    const float* w = (const float*)d_in[1];
    float* out = (float*)d_out;

    prep_x<<<dim3(LEN / 64, BATCH), 512>>>(x);
    prep_zero<<<(BATCH * 768 * 8 + 255) / 256, 256>>>();
    prep_w<<<(K_TAPS * 4 * 8 * 32 + 255) / 256, 256>>>(w);

    cudaFuncSetAttribute(conv_mma, cudaFuncAttributeMaxDynamicSharedMemorySize,
                         SMEM_BYTES);
    conv_mma<<<dim3(8, BATCH), THREADS, SMEM_BYTES>>>(out);
}

// round 13
// speedup vs baseline: 4.2219x; 1.4967x over previous
#include <cuda_runtime.h>
#include <cuda_fp16.h>
#include <cstdint>

// SparseConv1D as 32 shifted GEMMs via mma.sync fp16, 2-split weights:
//   out = (w_hi + w_lo) * x_fp16 ; x single fp16 (err 2^-12 -> ~1.5e-4 agg),
//   w split so weight error is negligible. 2 mma terms (was 3 with bf16).
// Single window pass; per-tap B staged in smem via cp.async double buffer.

#define LEN 4096
#define CIN 64
#define COUT 64
#define BATCH 16
#define K_TAPS 32
#define PADLEN 4864
#define THREADS 512
#define WROWS 1280
#define RSTRIDE 144
#define WINBYTES (WROWS * RSTRIDE)          // 184320
#define BSM_BYTES (2 * 16384)
#define SMEM_BYTES (WINBYTES + BSM_BYTES)   // 217088

__device__ __align__(16) __half g_x[(size_t)BATCH * PADLEN * CIN];
__device__ __align__(16) uint2 g_wf[K_TAPS * 2 * 4 * 8 * 32];  // [tap][v][k][..]

__constant__ int c_sk[K_TAPS] = {
    -512,-256,-128,-96,-64,-48,-32,-24,-16,-12,-8,-6,-4,-3,-2,-1,
     0,1,2,3,4,6,8,12,16,24,32,48,64,96,128,256
};

__device__ __forceinline__ unsigned smem_u32(const void* p) {
    unsigned a;
    asm("{ .reg .u64 t; cvta.to.shared.u64 t, %1; cvt.u32.u64 %0, t; }"
        : "=r"(a) : "l"(p));
    return a;
}
__device__ __forceinline__ void cp16(unsigned d, const void* s) {
    asm volatile("cp.async.cg.shared.global [%0], [%1], 16;" :: "r"(d), "l"(s));
}
__device__ __forceinline__ void cpc()  { asm volatile("cp.async.commit_group;"); }
__device__ __forceinline__ void cpw0() { asm volatile("cp.async.wait_group 0;"); }
__device__ __forceinline__ void ldmA(unsigned* r, unsigned addr) {
    asm volatile("ldmatrix.sync.aligned.m8n8.x4.shared.b16 {%0,%1,%2,%3}, [%4];"
        : "=r"(r[0]), "=r"(r[1]), "=r"(r[2]), "=r"(r[3]) : "r"(addr));
}
__device__ __forceinline__ void mma16816(float* d, const unsigned* a, uint2 b) {
    asm volatile(
        "mma.sync.aligned.m16n8k16.row.col.f32.f16.f16.f32 "
        "{%0,%1,%2,%3}, {%4,%5,%6,%7}, {%8,%9}, {%0,%1,%2,%3};"
        : "+f"(d[0]), "+f"(d[1]), "+f"(d[2]), "+f"(d[3])
        : "r"(a[0]), "r"(a[1]), "r"(a[2]), "r"(a[3]), "r"(b.x), "r"(b.y));
}
__device__ __forceinline__ unsigned pk(__half a, __half b) {
    __half2 t(a, b);
    return *reinterpret_cast<unsigned*>(&t);
}

// ---- prepass: transpose x -> [b][pos][ch] fp16, padded ----
__global__ __launch_bounds__(512) void prep_x(const float* __restrict__ x) {
    __shared__ float tile[64][65];
    const int p0 = blockIdx.x * 64, b = blockIdx.y, tid = threadIdx.x;
#pragma unroll
    for (int it = 0; it < 8; ++it) {
        int e = tid + it * 512;
        int ch = e >> 6, pos = e & 63;
        tile[ch][pos] = x[((size_t)b * CIN + ch) * LEN + p0 + pos];
    }
    __syncthreads();
    const int j = tid & 7, pp = tid >> 3;
    __half h[8];
#pragma unroll
    for (int c = 0; c < 8; ++c) h[c] = __float2half(tile[j * 8 + c][pp]);
    size_t off = ((size_t)b * PADLEN + 512 + p0 + pp) * CIN + j * 8;
    *reinterpret_cast<uint4*>(g_x + off) =
        make_uint4(pk(h[0],h[1]), pk(h[2],h[3]), pk(h[4],h[5]), pk(h[6],h[7]));
}
__global__ void prep_zero() {
    int idx = blockIdx.x * blockDim.x + threadIdx.x;
    if (idx >= BATCH * 768 * 8) return;
    int j = idx & 7, r = (idx >> 3) % 768, b = idx / (768 * 8);
    int pp = (r < 512) ? r : r + 4096;
    *reinterpret_cast<uint4*>(g_x + ((size_t)b * PADLEN + pp) * CIN + j * 8) =
        make_uint4(0, 0, 0, 0);
}
// weights fragment-packed, v0 = w_hi (fp16), v1 = w_lo = w - w_hi
__global__ void prep_w(const float* __restrict__ w) {
    int idx = blockIdx.x * blockDim.x + threadIdx.x;
    if (idx >= K_TAPS * 4 * 8 * 32) return;
    int lane = idx & 31, nt = (idx >> 5) & 7, kt = (idx >> 8) & 3, t = idx >> 10;
    int n = nt * 8 + (lane >> 2);
    int k = kt * 16 + (lane & 3) * 2;
    float v0 = w[((size_t)n * CIN + k)     * K_TAPS + t];
    float v1 = w[((size_t)n * CIN + k + 1) * K_TAPS + t];
    float v8 = w[((size_t)n * CIN + k + 8) * K_TAPS + t];
    float v9 = w[((size_t)n * CIN + k + 9) * K_TAPS + t];
    __half h0 = __float2half(v0), h1 = __float2half(v1);
    __half h8 = __float2half(v8), h9 = __float2half(v9);
    size_t base = ((size_t)(t * 2) * 4 + kt) * 256 + nt * 32 + lane;
    g_wf[base] = make_uint2(pk(h0, h1), pk(h8, h9));
    __half l0 = __float2half(v0 - __half2float(h0));
    __half l1 = __float2half(v1 - __half2float(h1));
    __half l8 = __float2half(v8 - __half2float(h8));
    __half l9 = __float2half(v9 - __half2float(h9));
    g_wf[base + 4 * 256] = make_uint2(pk(l0, l1), pk(l8, l9));
}

// ---- main kernel ----
struct Ctx {
    unsigned win_s, bsm_s;
    const uint2* bsm;
    int wid, lane, lrow, lcolb, tid;
};

__device__ __forceinline__ void ldaS(const Ctx& c, unsigned (&a)[2][4], int s) {
    const int rowb = c.wid * 32 + c_sk[s >> 2] + 512;
    const int k = s & 3;
    const unsigned base =
        c.win_s + (unsigned)((rowb + c.lrow) * RSTRIDE + k * 32 + c.lcolb);
    ldmA(a[0], base);
    ldmA(a[1], base + 16 * RSTRIDE);
}
__device__ __forceinline__ void loadBsm(const Ctx& c, const uint2* bb,
                                        uint2 (&b)[4], int v, int k, int h) {
    const uint2* p = bb + (v * 4 + k) * 256 + h * 128 + c.lane;
#pragma unroll
    for (int i = 0; i < 4; ++i) b[i] = p[i * 32];
}

__global__ __launch_bounds__(THREADS, 1)
void conv_mma(float* __restrict__ out) {
    extern __shared__ __align__(16) char smem[];
    const int tid = threadIdx.x, wid = tid >> 5, lane = tid & 31;
    const int st = blockIdx.x, b = blockIdx.y;
    const int P0 = st * 512;

    Ctx c;
    c.win_s = smem_u32(smem);
    c.bsm_s = c.win_s + WINBYTES;
    c.bsm   = reinterpret_cast<const uint2*>(smem + WINBYTES);
    c.wid = wid; c.lane = lane; c.tid = tid;
    c.lrow = lane & 15;
    c.lcolb = ((lane >> 4) * 8) * 2;

    float acc[2][8][4];
#pragma unroll
    for (int mt = 0; mt < 2; ++mt)
#pragma unroll
        for (int n = 0; n < 8; ++n)
#pragma unroll
            for (int q = 0; q < 4; ++q) acc[mt][n][q] = 0.f;

    // ---- fill window + B(tap 0) ----
    const __half* base = g_x + ((size_t)b * PADLEN + P0) * CIN;
#pragma unroll
    for (int it = 0; it < (WROWS * 8) / THREADS; ++it) {
        int cc = tid + it * THREADS;
        int row = cc >> 3, ch = cc & 7;
        cp16(c.win_s + row * RSTRIDE + ch * 16, base + row * CIN + ch * 8);
    }
    const char* wsrc = (const char*)g_wf;
#pragma unroll
    for (int q = 0; q < 2; ++q) {
        int cc = tid + q * THREADS;
        cp16(c.bsm_s + cc * 16, wsrc + cc * 16);
    }
    cpc(); cpw0();
    __syncthreads();

    unsigned a[2][2][4];
    uint2 bf[2][4];
    ldaS(c, a[0], 0);
    loadBsm(c, c.bsm, bf[0], 0, 0, 0);

    for (int t = 0; t < K_TAPS; ++t) {
        const int buf = t & 1;
        const uint2* bb = c.bsm + buf * 2048;
        if (t + 1 < K_TAPS) {          // async next tap's 16 KB B
            const char* src = wsrc + (size_t)(t + 1) * 16384;
            const unsigned dst = c.bsm_s + (buf ^ 1) * 16384;
#pragma unroll
            for (int q = 0; q < 2; ++q) {
                int cc = tid + q * THREADS;
                cp16(dst + cc * 16, src + cc * 16);
            }
            cpc();
        }
#pragma unroll
        for (int k = 0; k < 4; ++k) {
            const int s = t * 4 + k;
            unsigned (&aC)[2][4] = a[k & 1];
            unsigned (&aN)[2][4] = a[(k + 1) & 1];
#pragma unroll
            for (int u = 0; u < 4; ++u) {          // v = u>>1, half = u&1
                const int m = k * 4 + u;
                uint2 (&cur)[4] = bf[m & 1];
                uint2 (&nxt)[4] = bf[(m + 1) & 1];
                if (u == 0 && s + 1 < 4 * K_TAPS) ldaS(c, aN, s + 1);
                if (m + 1 < 16) {
                    const int m2 = m + 1;
                    const int k2 = m2 >> 2, u2 = m2 & 3;
                    loadBsm(c, bb, nxt, u2 >> 1, k2, u2 & 1);
                }
                const int h = u & 1;
#pragma unroll
                for (int i = 0; i < 4; ++i)
#pragma unroll
                    for (int mt = 0; mt < 2; ++mt)
                        mma16816(acc[mt][h * 4 + i], aC[mt], cur[i]);
            }
        }
        cpw0();
        __syncthreads();
        if (t + 1 < K_TAPS)
            loadBsm(c, c.bsm + (buf ^ 1) * 2048, bf[0], 0, 0, 0);
    }

    // ---- store D fragments ----
    const int g = lane >> 2, c0 = (lane & 3) * 2;
#pragma unroll
    for (int mt = 0; mt < 2; ++mt) {
        const int pos = P0 + wid * 32 + mt * 16 + g;
#pragma unroll
        for (int n = 0; n < 8; ++n) {
            const int o = n * 8 + c0;
            float* q0 = out + ((size_t)b * COUT + o) * LEN;
            float* q1 = out + ((size_t)b * COUT + o + 1) * LEN;
            q0[pos]     = acc[mt][n][0];
            q1[pos]     = acc[mt][n][1];
            q0[pos + 8] = acc[mt][n][2];
            q1[pos + 8] = acc[mt][n][3];
        }
    }
}

extern "C" void kernel_launch(void* const* d_in, const int* in_sizes, int n_in,
                              void* d_out, int out_size) {
    const float* x = (const float*)d_in[0];
    const float* w = (const float*)d_in[1];
    float* out = (float*)d_out;

    prep_x<<<dim3(LEN / 64, BATCH), 512>>>(x);
    prep_zero<<<(BATCH * 768 * 8 + 255) / 256, 256>>>();
    prep_w<<<(K_TAPS * 4 * 8 * 32 + 255) / 256, 256>>>(w);

    cudaFuncSetAttribute(conv_mma, cudaFuncAttributeMaxDynamicSharedMemorySize,
                         SMEM_BYTES);
    conv_mma<<<dim3(8, BATCH), THREADS, SMEM_BYTES>>>(out);
}

// round 14
// speedup vs baseline: 6.6799x; 1.5822x over previous
#include <cuda_runtime.h>
#include <cuda_fp16.h>
#include <cstdint>

// SparseConv1D as 32 shifted GEMMs via mma.sync fp16, single term:
//   out = w_fp16 * x_fp16 ; both rounded to fp16 (each ~2^-12 rel);
//   measured single-source error 2.08e-4 -> predicted ~3e-4 < 1e-3.
// Single window pass; per-tap 8KB B staged in smem via cp.async double buffer.

#define LEN 4096
#define CIN 64
#define COUT 64
#define BATCH 16
#define K_TAPS 32
#define PADLEN 4864
#define THREADS 512
#define WROWS 1280
#define RSTRIDE 144
#define WINBYTES (WROWS * RSTRIDE)          // 184320
#define BSM_BYTES (2 * 8192)
#define SMEM_BYTES (WINBYTES + BSM_BYTES)   // 200704

__device__ __align__(16) __half g_x[(size_t)BATCH * PADLEN * CIN];
__device__ __align__(16) uint2 g_wf[K_TAPS * 4 * 8 * 32];   // [tap][k][nt][lane]

__constant__ int c_sk[K_TAPS] = {
    -512,-256,-128,-96,-64,-48,-32,-24,-16,-12,-8,-6,-4,-3,-2,-1,
     0,1,2,3,4,6,8,12,16,24,32,48,64,96,128,256
};

__device__ __forceinline__ unsigned smem_u32(const void* p) {
    unsigned a;
    asm("{ .reg .u64 t; cvta.to.shared.u64 t, %1; cvt.u32.u64 %0, t; }"
        : "=r"(a) : "l"(p));
    return a;
}
__device__ __forceinline__ void cp16(unsigned d, const void* s) {
    asm volatile("cp.async.cg.shared.global [%0], [%1], 16;" :: "r"(d), "l"(s));
}
__device__ __forceinline__ void cpc()  { asm volatile("cp.async.commit_group;"); }
__device__ __forceinline__ void cpw0() { asm volatile("cp.async.wait_group 0;"); }
__device__ __forceinline__ void ldmA(unsigned* r, unsigned addr) {
    asm volatile("ldmatrix.sync.aligned.m8n8.x4.shared.b16 {%0,%1,%2,%3}, [%4];"
        : "=r"(r[0]), "=r"(r[1]), "=r"(r[2]), "=r"(r[3]) : "r"(addr));
}
__device__ __forceinline__ void mma16816(float* d, const unsigned* a, uint2 b) {
    asm volatile(
        "mma.sync.aligned.m16n8k16.row.col.f32.f16.f16.f32 "
        "{%0,%1,%2,%3}, {%4,%5,%6,%7}, {%8,%9}, {%0,%1,%2,%3};"
        : "+f"(d[0]), "+f"(d[1]), "+f"(d[2]), "+f"(d[3])
        : "r"(a[0]), "r"(a[1]), "r"(a[2]), "r"(a[3]), "r"(b.x), "r"(b.y));
}
__device__ __forceinline__ unsigned pk(__half a, __half b) {
    __half2 t(a, b);
    return *reinterpret_cast<unsigned*>(&t);
}

// ---- prepass: transpose x -> [b][pos][ch] fp16, padded ----
__global__ __launch_bounds__(512) void prep_x(const float* __restrict__ x) {
    __shared__ float tile[64][65];
    const int p0 = blockIdx.x * 64, b = blockIdx.y, tid = threadIdx.x;
#pragma unroll
    for (int it = 0; it < 8; ++it) {
        int e = tid + it * 512;
        int ch = e >> 6, pos = e & 63;
        tile[ch][pos] = x[((size_t)b * CIN + ch) * LEN + p0 + pos];
    }
    __syncthreads();
    const int j = tid & 7, pp = tid >> 3;
    __half h[8];
#pragma unroll
    for (int c = 0; c < 8; ++c) h[c] = __float2half(tile[j * 8 + c][pp]);
    size_t off = ((size_t)b * PADLEN + 512 + p0 + pp) * CIN + j * 8;
    *reinterpret_cast<uint4*>(g_x + off) =
        make_uint4(pk(h[0],h[1]), pk(h[2],h[3]), pk(h[4],h[5]), pk(h[6],h[7]));
}
__global__ void prep_zero() {
    int idx = blockIdx.x * blockDim.x + threadIdx.x;
    if (idx >= BATCH * 768 * 8) return;
    int j = idx & 7, r = (idx >> 3) % 768, b = idx / (768 * 8);
    int pp = (r < 512) ? r : r + 4096;
    *reinterpret_cast<uint4*>(g_x + ((size_t)b * PADLEN + pp) * CIN + j * 8) =
        make_uint4(0, 0, 0, 0);
}
__global__ void prep_w(const float* __restrict__ w) {
    int idx = blockIdx.x * blockDim.x + threadIdx.x;
    if (idx >= K_TAPS * 4 * 8 * 32) return;
    int lane = idx & 31, nt = (idx >> 5) & 7, kt = (idx >> 8) & 3, t = idx >> 10;
    int n = nt * 8 + (lane >> 2);
    int k = kt * 16 + (lane & 3) * 2;
    __half h0 = __float2half(w[((size_t)n * CIN + k)     * K_TAPS + t]);
    __half h1 = __float2half(w[((size_t)n * CIN + k + 1) * K_TAPS + t]);
    __half h8 = __float2half(w[((size_t)n * CIN + k + 8) * K_TAPS + t]);
    __half h9 = __float2half(w[((size_t)n * CIN + k + 9) * K_TAPS + t]);
    g_wf[((size_t)t * 4 + kt) * 256 + nt * 32 + lane] =
        make_uint2(pk(h0, h1), pk(h8, h9));
}

// ---- main kernel ----
struct Ctx {
    unsigned win_s, bsm_s;
    const uint2* bsm;
    int wid, lane, lrow, lcolb, tid;
};

__device__ __forceinline__ void ldaS(const Ctx& c, unsigned (&a)[2][4], int s) {
    const int rowb = c.wid * 32 + c_sk[s >> 2] + 512;
    const int k = s & 3;
    const unsigned base =
        c.win_s + (unsigned)((rowb + c.lrow) * RSTRIDE + k * 32 + c.lcolb);
    ldmA(a[0], base);
    ldmA(a[1], base + 16 * RSTRIDE);
}
__device__ __forceinline__ void loadBsm(const Ctx& c, const uint2* bb,
                                        uint2 (&b)[4], int k, int h) {
    const uint2* p = bb + k * 256 + h * 128 + c.lane;
#pragma unroll
    for (int i = 0; i < 4; ++i) b[i] = p[i * 32];
}

__global__ __launch_bounds__(THREADS, 1)
void conv_mma(float* __restrict__ out) {
    extern __shared__ __align__(16) char smem[];
    const int tid = threadIdx.x, wid = tid >> 5, lane = tid & 31;
    const int st = blockIdx.x, b = blockIdx.y;
    const int P0 = st * 512;

    Ctx c;
    c.win_s = smem_u32(smem);
    c.bsm_s = c.win_s + WINBYTES;
    c.bsm   = reinterpret_cast<const uint2*>(smem + WINBYTES);
    c.wid = wid; c.lane = lane; c.tid = tid;
    c.lrow = lane & 15;
    c.lcolb = ((lane >> 4) * 8) * 2;

    float acc[2][8][4];
#pragma unroll
    for (int mt = 0; mt < 2; ++mt)
#pragma unroll
        for (int n = 0; n < 8; ++n)
#pragma unroll
            for (int q = 0; q < 4; ++q) acc[mt][n][q] = 0.f;

    // ---- fill window + B(tap 0) ----
    const __half* base = g_x + ((size_t)b * PADLEN + P0) * CIN;
#pragma unroll
    for (int it = 0; it < (WROWS * 8) / THREADS; ++it) {
        int cc = tid + it * THREADS;
        int row = cc >> 3, ch = cc & 7;
        cp16(c.win_s + row * RSTRIDE + ch * 16, base + row * CIN + ch * 8);
    }
    const char* wsrc = (const char*)g_wf;
    cp16(c.bsm_s + tid * 16, wsrc + tid * 16);
    cpc(); cpw0();
    __syncthreads();

    unsigned a[2][2][4];
    uint2 bf[2][4];
    ldaS(c, a[0], 0);
    loadBsm(c, c.bsm, bf[0], 0, 0);

    for (int t = 0; t < K_TAPS; ++t) {
        const int buf = t & 1;
        const uint2* bb = c.bsm + buf * 1024;
        if (t + 1 < K_TAPS) {          // async next tap's 8 KB B
            cp16(c.bsm_s + (buf ^ 1) * 8192 + tid * 16,
                 wsrc + (size_t)(t + 1) * 8192 + tid * 16);
            cpc();
        }
#pragma unroll
        for (int k = 0; k < 4; ++k) {
            const int s = t * 4 + k;
            unsigned (&aC)[2][4] = a[k & 1];
            unsigned (&aN)[2][4] = a[(k + 1) & 1];
#pragma unroll
            for (int u = 0; u < 2; ++u) {          // n-half
                const int m = k * 2 + u;
                uint2 (&cur)[4] = bf[m & 1];
                uint2 (&nxt)[4] = bf[(m + 1) & 1];
                if (u == 0 && s + 1 < 4 * K_TAPS) ldaS(c, aN, s + 1);
                if (m + 1 < 8) {
                    const int m2 = m + 1;
                    loadBsm(c, bb, nxt, m2 >> 1, m2 & 1);
                }
#pragma unroll
                for (int i = 0; i < 4; ++i)
#pragma unroll
                    for (int mt = 0; mt < 2; ++mt)
                        mma16816(acc[mt][u * 4 + i], aC[mt], cur[i]);
            }
        }
        cpw0();
        __syncthreads();
        if (t + 1 < K_TAPS)
            loadBsm(c, c.bsm + (buf ^ 1) * 1024, bf[0], 0, 0);
    }

    // ---- store D fragments ----
    const int g = lane >> 2, c0 = (lane & 3) * 2;
#pragma unroll
    for (int mt = 0; mt < 2; ++mt) {
        const int pos = P0 + wid * 32 + mt * 16 + g;
#pragma unroll
        for (int n = 0; n < 8; ++n) {
            const int o = n * 8 + c0;
            float* q0 = out + ((size_t)b * COUT + o) * LEN;
            float* q1 = out + ((size_t)b * COUT + o + 1) * LEN;
            q0[pos]     = acc[mt][n][0];
            q1[pos]     = acc[mt][n][1];
            q0[pos + 8] = acc[mt][n][2];
            q1[pos + 8] = acc[mt][n][3];
        }
    }
}

extern "C" void kernel_launch(void* const* d_in, const int* in_sizes, int n_in,
                              void* d_out, int out_size) {
    const float* x = (const float*)d_in[0];
    const float* w = (const float*)d_in[1];
    float* out = (float*)d_out;

    prep_x<<<dim3(LEN / 64, BATCH), 512>>>(x);
    prep_zero<<<(BATCH * 768 * 8 + 255) / 256, 256>>>();
    prep_w<<<(K_TAPS * 4 * 8 * 32 + 255) / 256, 256>>>(w);

    cudaFuncSetAttribute(conv_mma, cudaFuncAttributeMaxDynamicSharedMemorySize,
                         SMEM_BYTES);
    conv_mma<<<dim3(8, BATCH), THREADS, SMEM_BYTES>>>(out);
}